// round 1
// baseline (speedup 1.0000x reference)
#include <cuda_runtime.h>
#include <math.h>

#define T_  2048
#define D_  1024
#define I_  512
#define E_  32
#define K_  6
#define SI_ 1024

#define BM 64
#define BN 128
#define BK 16

// ---------------- scratch (no allocations allowed) ----------------
__device__ float g_zh[T_ * SI_];          // shared-expert hidden  (8 MB)
__device__ float g_hs[T_ * K_ * I_];      // routed hidden per slot (25 MB)
__device__ int   g_cnt[E_];               // tokens per expert
__device__ int   g_slots[E_ * T_];        // slot ids (t*K+k) per expert
__device__ int   g_tidx[T_ * K_];         // chosen expert per (t,k)
__device__ float g_tval[T_ * K_];         // gate value per (t,k)

// ---------------- init ----------------
__global__ void moe_init_kernel() {
    if (threadIdx.x < E_) g_cnt[threadIdx.x] = 0;
}

// ---------------- router: 1 warp per token ----------------
__global__ __launch_bounds__(256) void moe_router_kernel(
    const float* __restrict__ x,
    const float* __restrict__ rw,
    const float* __restrict__ rb)
{
    __shared__ float sh[8][32];
    const int wi   = threadIdx.x >> 5;
    const int lane = threadIdx.x & 31;
    const int t    = blockIdx.x * 8 + wi;

    const float4* xr = (const float4*)(x + (size_t)t * D_);
    // logits: per expert, all 32 lanes cooperate (coalesced), warp-reduce
    for (int e = 0; e < E_; e++) {
        const float4* wr = (const float4*)(rw + (size_t)e * D_);
        float acc = 0.f;
        #pragma unroll 4
        for (int d = lane; d < D_ / 4; d += 32) {
            float4 a = xr[d], b = wr[d];
            acc += a.x * b.x + a.y * b.y + a.z * b.z + a.w * b.w;
        }
        #pragma unroll
        for (int off = 16; off; off >>= 1)
            acc += __shfl_down_sync(0xffffffffu, acc, off);
        if (lane == 0) sh[wi][e] = acc + rb[e];
    }
    __syncwarp();
    float logit = sh[wi][lane];

    // warp softmax over 32 experts (fp32)
    float mx = logit;
    #pragma unroll
    for (int off = 16; off; off >>= 1)
        mx = fmaxf(mx, __shfl_xor_sync(0xffffffffu, mx, off));
    float p = expf(logit - mx);
    float sm = p;
    #pragma unroll
    for (int off = 16; off; off >>= 1)
        sm += __shfl_xor_sync(0xffffffffu, sm, off);
    float score = p / sm;

    // group score = sum of top-2 of 4 experts in group (group = lane>>2)
    const int grp = lane >> 2;
    float v0 = __shfl_sync(0xffffffffu, score, grp * 4 + 0);
    float v1 = __shfl_sync(0xffffffffu, score, grp * 4 + 1);
    float v2 = __shfl_sync(0xffffffffu, score, grp * 4 + 2);
    float v3 = __shfl_sync(0xffffffffu, score, grp * 4 + 3);
    float a  = fmaxf(v0, v1), b  = fminf(v0, v1);
    float c  = fmaxf(v2, v3), dd = fminf(v2, v3);
    float top2 = (a >= c) ? (a + fmaxf(b, c)) : (c + fmaxf(a, dd));

    // top-4 groups of 8 (strict >, lower index wins on ties like jax)
    float gsa[8];
    #pragma unroll
    for (int j = 0; j < 8; j++) gsa[j] = __shfl_sync(0xffffffffu, top2, j * 4);
    unsigned keep = 0;
    #pragma unroll
    for (int it = 0; it < 4; it++) {
        float bv = -1e30f; int bj = 0;
        #pragma unroll
        for (int j = 0; j < 8; j++) {
            bool cand = (((keep >> j) & 1u) == 0u) && (gsa[j] > bv);
            if (cand) { bv = gsa[j]; bj = j; }
        }
        keep |= 1u << bj;
    }

    float msc = ((keep >> grp) & 1u) ? score : -1e30f;
    __syncwarp();
    sh[wi][lane] = msc;
    __syncwarp();

    if (lane == 0) {
        #pragma unroll
        for (int kk = 0; kk < K_; kk++) {
            float bv = -1e30f; int be = 0;
            for (int ee = 0; ee < 32; ee++) {
                float s = sh[wi][ee];
                if (s > bv) { bv = s; be = ee; }
            }
            sh[wi][be] = -2e30f;
            g_tidx[t * K_ + kk] = be;
            g_tval[t * K_ + kk] = bv;                 // masked == original for kept groups
            int pos = atomicAdd(&g_cnt[be], 1);
            g_slots[be * T_ + pos] = t * K_ + kk;     // slot id encodes token & k
        }
    }
}

// ---------------- shared expert: zh = silu((x@sw1+sb1)*(x@sw2+sb2)) ----------------
__global__ __launch_bounds__(256) void moe_shared_h_kernel(
    const float* __restrict__ x,
    const float* __restrict__ sw1, const float* __restrict__ sb1,
    const float* __restrict__ sw2, const float* __restrict__ sb2)
{
    __shared__ float As[BK][BM];
    __shared__ float B1s[BK][BN];
    __shared__ float B2s[BK][BN];

    const int tid = threadIdx.x;
    const int tx = tid & 15, ty = tid >> 4;
    const int mb = blockIdx.y * BM, nb = blockIdx.x * BN;
    const int am = tid >> 2, ak = (tid & 3) << 2;
    const int bk = tid >> 4, bn = (tid & 15) << 3;

    float acc1[4][8] = {}, acc2[4][8] = {};

    const float* Ap  = x   + (size_t)(mb + am) * D_  + ak;
    const float* B1p = sw1 + (size_t)bk * SI_ + nb + bn;
    const float* B2p = sw2 + (size_t)bk * SI_ + nb + bn;

    for (int k0 = 0; k0 < D_; k0 += BK) {
        float4 a4 = *(const float4*)(Ap + k0);
        As[ak][am] = a4.x; As[ak + 1][am] = a4.y; As[ak + 2][am] = a4.z; As[ak + 3][am] = a4.w;
        float4 b1a = *(const float4*)(B1p + (size_t)k0 * SI_);
        float4 b1b = *(const float4*)(B1p + (size_t)k0 * SI_ + 4);
        *(float4*)&B1s[bk][bn] = b1a; *(float4*)&B1s[bk][bn + 4] = b1b;
        float4 b2a = *(const float4*)(B2p + (size_t)k0 * SI_);
        float4 b2b = *(const float4*)(B2p + (size_t)k0 * SI_ + 4);
        *(float4*)&B2s[bk][bn] = b2a; *(float4*)&B2s[bk][bn + 4] = b2b;
        __syncthreads();
        #pragma unroll
        for (int k = 0; k < BK; k++) {
            float ar[4], b1r[8], b2r[8];
            #pragma unroll
            for (int i = 0; i < 4; i++) ar[i] = As[k][ty * 4 + i];
            #pragma unroll
            for (int j = 0; j < 8; j++) { b1r[j] = B1s[k][tx * 8 + j]; b2r[j] = B2s[k][tx * 8 + j]; }
            #pragma unroll
            for (int i = 0; i < 4; i++)
                #pragma unroll
                for (int j = 0; j < 8; j++) {
                    acc1[i][j] = fmaf(ar[i], b1r[j], acc1[i][j]);
                    acc2[i][j] = fmaf(ar[i], b2r[j], acc2[i][j]);
                }
        }
        __syncthreads();
    }
    #pragma unroll
    for (int i = 0; i < 4; i++) {
        int row = mb + ty * 4 + i;
        #pragma unroll
        for (int j = 0; j < 8; j++) {
            int n = nb + tx * 8 + j;
            float h1 = acc1[i][j] + sb1[n];
            float h2 = acc2[i][j] + sb2[n];
            float pp = h1 * h2;
            g_zh[(size_t)row * SI_ + n] = pp / (1.f + expf(-pp));
        }
    }
}

// ---------------- out = zh@sw3 + sb3 + sum_k gate_k * b3[e_k] ----------------
__global__ __launch_bounds__(256) void moe_out_init_kernel(
    const float* __restrict__ sw3, const float* __restrict__ sb3,
    const float* __restrict__ b3, float* __restrict__ out)
{
    __shared__ float As[BK][BM];
    __shared__ float Bs[BK][BN];

    const int tid = threadIdx.x;
    const int tx = tid & 15, ty = tid >> 4;
    const int mb = blockIdx.y * BM, nb = blockIdx.x * BN;
    const int am = tid >> 2, ak = (tid & 3) << 2;
    const int bk = tid >> 4, bn = (tid & 15) << 3;

    float acc[4][8] = {};

    const float* Ap = g_zh + (size_t)(mb + am) * SI_ + ak;
    const float* Bp = sw3  + (size_t)bk * D_ + nb + bn;

    for (int k0 = 0; k0 < SI_; k0 += BK) {
        float4 a4 = *(const float4*)(Ap + k0);
        As[ak][am] = a4.x; As[ak + 1][am] = a4.y; As[ak + 2][am] = a4.z; As[ak + 3][am] = a4.w;
        float4 ba = *(const float4*)(Bp + (size_t)k0 * D_);
        float4 bb = *(const float4*)(Bp + (size_t)k0 * D_ + 4);
        *(float4*)&Bs[bk][bn] = ba; *(float4*)&Bs[bk][bn + 4] = bb;
        __syncthreads();
        #pragma unroll
        for (int k = 0; k < BK; k++) {
            float ar[4], br[8];
            #pragma unroll
            for (int i = 0; i < 4; i++) ar[i] = As[k][ty * 4 + i];
            #pragma unroll
            for (int j = 0; j < 8; j++) br[j] = Bs[k][tx * 8 + j];
            #pragma unroll
            for (int i = 0; i < 4; i++)
                #pragma unroll
                for (int j = 0; j < 8; j++)
                    acc[i][j] = fmaf(ar[i], br[j], acc[i][j]);
        }
        __syncthreads();
    }
    #pragma unroll
    for (int i = 0; i < 4; i++) {
        int row = mb + ty * 4 + i;
        float ex[8];
        #pragma unroll
        for (int j = 0; j < 8; j++) ex[j] = sb3[nb + tx * 8 + j];
        #pragma unroll
        for (int kk = 0; kk < K_; kk++) {
            int   idx = g_tidx[row * K_ + kk];
            float val = g_tval[row * K_ + kk];
            const float* br = b3 + (size_t)idx * D_ + nb + tx * 8;
            float4 u = ((const float4*)br)[0];
            float4 w = ((const float4*)br)[1];
            ex[0] = fmaf(val, u.x, ex[0]); ex[1] = fmaf(val, u.y, ex[1]);
            ex[2] = fmaf(val, u.z, ex[2]); ex[3] = fmaf(val, u.w, ex[3]);
            ex[4] = fmaf(val, w.x, ex[4]); ex[5] = fmaf(val, w.y, ex[5]);
            ex[6] = fmaf(val, w.z, ex[6]); ex[7] = fmaf(val, w.w, ex[7]);
        }
        #pragma unroll
        for (int j = 0; j < 8; j++)
            out[(size_t)row * D_ + nb + tx * 8 + j] = acc[i][j] + ex[j];
    }
}

// ---------------- routed experts stage 1: hs = gate * silu((xW1+b1)*(xW2+b2)) ----------------
__global__ __launch_bounds__(256) void moe_routed_h_kernel(
    const float* __restrict__ x,
    const float* __restrict__ W1, const float* __restrict__ b1,
    const float* __restrict__ W2, const float* __restrict__ b2)
{
    const int e   = blockIdx.z;
    const int cnt = g_cnt[e];
    const int mb  = blockIdx.y * BM;
    if (mb >= cnt) return;
    const int nb  = blockIdx.x * BN;

    __shared__ float As[BK][BM];
    __shared__ float B1s[BK][BN];
    __shared__ float B2s[BK][BN];
    __shared__ int   slotS[BM];

    const int tid = threadIdx.x;
    if (tid < BM) {
        int m = mb + tid;
        slotS[tid] = (m < cnt) ? g_slots[e * T_ + m] : g_slots[e * T_];
    }
    __syncthreads();

    const int tx = tid & 15, ty = tid >> 4;
    const int am = tid >> 2, ak = (tid & 3) << 2;
    const int bk = tid >> 4, bn = (tid & 15) << 3;

    float acc1[4][8] = {}, acc2[4][8] = {};

    const float* Ap  = x + (size_t)(slotS[am] / K_) * D_ + ak;
    const float* W1b = W1 + (size_t)e * D_ * I_ + (size_t)bk * I_ + nb + bn;
    const float* W2b = W2 + (size_t)e * D_ * I_ + (size_t)bk * I_ + nb + bn;

    for (int k0 = 0; k0 < D_; k0 += BK) {
        float4 a4 = *(const float4*)(Ap + k0);
        As[ak][am] = a4.x; As[ak + 1][am] = a4.y; As[ak + 2][am] = a4.z; As[ak + 3][am] = a4.w;
        float4 b1a = *(const float4*)(W1b + (size_t)k0 * I_);
        float4 b1b = *(const float4*)(W1b + (size_t)k0 * I_ + 4);
        *(float4*)&B1s[bk][bn] = b1a; *(float4*)&B1s[bk][bn + 4] = b1b;
        float4 b2a = *(const float4*)(W2b + (size_t)k0 * I_);
        float4 b2b = *(const float4*)(W2b + (size_t)k0 * I_ + 4);
        *(float4*)&B2s[bk][bn] = b2a; *(float4*)&B2s[bk][bn + 4] = b2b;
        __syncthreads();
        #pragma unroll
        for (int k = 0; k < BK; k++) {
            float ar[4], b1r[8], b2r[8];
            #pragma unroll
            for (int i = 0; i < 4; i++) ar[i] = As[k][ty * 4 + i];
            #pragma unroll
            for (int j = 0; j < 8; j++) { b1r[j] = B1s[k][tx * 8 + j]; b2r[j] = B2s[k][tx * 8 + j]; }
            #pragma unroll
            for (int i = 0; i < 4; i++)
                #pragma unroll
                for (int j = 0; j < 8; j++) {
                    acc1[i][j] = fmaf(ar[i], b1r[j], acc1[i][j]);
                    acc2[i][j] = fmaf(ar[i], b2r[j], acc2[i][j]);
                }
        }
        __syncthreads();
    }
    #pragma unroll
    for (int i = 0; i < 4; i++) {
        int lm = ty * 4 + i;
        bool valid = (mb + lm) < cnt;
        int s = slotS[lm];
        float gv = g_tval[s];
        #pragma unroll
        for (int j = 0; j < 8; j++) {
            int n = nb + tx * 8 + j;
            float h1 = acc1[i][j] + b1[(size_t)e * I_ + n];
            float h2 = acc2[i][j] + b2[(size_t)e * I_ + n];
            float pp = h1 * h2;
            float hv = gv * pp / (1.f + expf(-pp));
            if (valid) g_hs[(size_t)s * I_ + n] = hv;
        }
    }
}

// ---------------- routed experts stage 2: out += hs @ W3[e] ----------------
__global__ __launch_bounds__(256) void moe_routed_out_kernel(
    const float* __restrict__ W3, float* __restrict__ out)
{
    const int e   = blockIdx.z;
    const int cnt = g_cnt[e];
    const int mb  = blockIdx.y * BM;
    if (mb >= cnt) return;
    const int nb  = blockIdx.x * BN;

    __shared__ float As[BK][BM];
    __shared__ float Bs[BK][BN];
    __shared__ int   slotS[BM];

    const int tid = threadIdx.x;
    if (tid < BM) {
        int m = mb + tid;
        slotS[tid] = (m < cnt) ? g_slots[e * T_ + m] : g_slots[e * T_];
    }
    __syncthreads();

    const int tx = tid & 15, ty = tid >> 4;
    const int am = tid >> 2, ak = (tid & 3) << 2;
    const int bk = tid >> 4, bn = (tid & 15) << 3;

    float acc[4][8] = {};

    const float* Ap = g_hs + (size_t)slotS[am] * I_ + ak;
    const float* Bp = W3 + (size_t)e * I_ * D_ + (size_t)bk * D_ + nb + bn;

    for (int k0 = 0; k0 < I_; k0 += BK) {
        float4 a4 = *(const float4*)(Ap + k0);
        As[ak][am] = a4.x; As[ak + 1][am] = a4.y; As[ak + 2][am] = a4.z; As[ak + 3][am] = a4.w;
        float4 ba = *(const float4*)(Bp + (size_t)k0 * D_);
        float4 bb = *(const float4*)(Bp + (size_t)k0 * D_ + 4);
        *(float4*)&Bs[bk][bn] = ba; *(float4*)&Bs[bk][bn + 4] = bb;
        __syncthreads();
        #pragma unroll
        for (int k = 0; k < BK; k++) {
            float ar[4], br[8];
            #pragma unroll
            for (int i = 0; i < 4; i++) ar[i] = As[k][ty * 4 + i];
            #pragma unroll
            for (int j = 0; j < 8; j++) br[j] = Bs[k][tx * 8 + j];
            #pragma unroll
            for (int i = 0; i < 4; i++)
                #pragma unroll
                for (int j = 0; j < 8; j++)
                    acc[i][j] = fmaf(ar[i], br[j], acc[i][j]);
        }
        __syncthreads();
    }
    #pragma unroll
    for (int i = 0; i < 4; i++) {
        int lm = ty * 4 + i;
        if ((mb + lm) < cnt) {
            int t = slotS[lm] / K_;
            #pragma unroll
            for (int j = 0; j < 8; j++) {
                int n = nb + tx * 8 + j;
                atomicAdd(&out[(size_t)t * D_ + n], acc[i][j]);
            }
        }
    }
}

// ---------------- launch ----------------
extern "C" void kernel_launch(void* const* d_in, const int* in_sizes, int n_in,
                              void* d_out, int out_size)
{
    (void)in_sizes; (void)n_in; (void)out_size;
    const float* x   = (const float*)d_in[0];
    const float* rw  = (const float*)d_in[1];
    const float* rb  = (const float*)d_in[2];
    const float* W1  = (const float*)d_in[3];
    const float* b1  = (const float*)d_in[4];
    const float* W2  = (const float*)d_in[5];
    const float* b2  = (const float*)d_in[6];
    const float* W3  = (const float*)d_in[7];
    const float* b3  = (const float*)d_in[8];
    const float* sw1 = (const float*)d_in[9];
    const float* sb1 = (const float*)d_in[10];
    const float* sw2 = (const float*)d_in[11];
    const float* sb2 = (const float*)d_in[12];
    const float* sw3 = (const float*)d_in[13];
    const float* sb3 = (const float*)d_in[14];
    float* out = (float*)d_out;

    moe_init_kernel<<<1, 32>>>();
    moe_router_kernel<<<T_ / 8, 256>>>(x, rw, rb);
    moe_shared_h_kernel<<<dim3(SI_ / BN, T_ / BM), 256>>>(x, sw1, sb1, sw2, sb2);
    moe_out_init_kernel<<<dim3(D_ / BN, T_ / BM), 256>>>(sw3, sb3, b3, out);
    moe_routed_h_kernel<<<dim3(I_ / BN, T_ / BM, E_), 256>>>(x, W1, b1, W2, b2);
    moe_routed_out_kernel<<<dim3(D_ / BN, T_ / BM, E_), 256>>>(W3, out);
}

// round 2
// speedup vs baseline: 2.9364x; 2.9364x over previous
#include <cuda_runtime.h>
#include <math.h>

#define T_  2048
#define D_  1024
#define I_  512
#define E_  32
#define K_  6
#define SI_ 1024

#define BM 64
#define BN 128
#define BK 16
#define ASTR 20     // A smem row stride (conflict-free frag loads: 20*g % 32 spans all banks)
#define BSTR 136    // B smem row stride (136 % 32 == 8 -> conflict-free frag loads)

// ---------------- scratch (no allocations allowed) ----------------
__device__ float g_zh[T_ * SI_];          // shared-expert hidden
__device__ float g_hs[T_ * K_ * I_];      // routed hidden per slot
__device__ int   g_cnt[E_];
__device__ int   g_slots[E_ * T_];        // slot ids (t*K+k) per expert
__device__ int   g_tidx[T_ * K_];
__device__ float g_tval[T_ * K_];

__device__ __forceinline__ unsigned f2tf(float f) {
    unsigned u;
    asm("cvt.rna.tf32.f32 %0, %1;" : "=r"(u) : "f"(f));
    return u;
}

#define MMA8(c, a, b0v, b1v) \
    asm volatile("mma.sync.aligned.m16n8k8.row.col.f32.tf32.tf32.f32 " \
        "{%0,%1,%2,%3},{%4,%5,%6,%7},{%8,%9},{%0,%1,%2,%3};" \
        : "+f"((c)[0]), "+f"((c)[1]), "+f"((c)[2]), "+f"((c)[3]) \
        : "r"((a)[0]), "r"((a)[1]), "r"((a)[2]), "r"((a)[3]), "r"(b0v), "r"(b1v))

// ---------------- init ----------------
__global__ void moe_init_kernel() {
    if (threadIdx.x < E_) g_cnt[threadIdx.x] = 0;
}

// ---------------- router: 1 warp per token (unchanged, validated) ----------------
__global__ __launch_bounds__(256) void moe_router_kernel(
    const float* __restrict__ x,
    const float* __restrict__ rw,
    const float* __restrict__ rb)
{
    __shared__ float sh[8][32];
    const int wi   = threadIdx.x >> 5;
    const int lane = threadIdx.x & 31;
    const int t    = blockIdx.x * 8 + wi;

    const float4* xr = (const float4*)(x + (size_t)t * D_);
    for (int e = 0; e < E_; e++) {
        const float4* wr = (const float4*)(rw + (size_t)e * D_);
        float acc = 0.f;
        #pragma unroll 4
        for (int d = lane; d < D_ / 4; d += 32) {
            float4 a = xr[d], b = wr[d];
            acc += a.x * b.x + a.y * b.y + a.z * b.z + a.w * b.w;
        }
        #pragma unroll
        for (int off = 16; off; off >>= 1)
            acc += __shfl_down_sync(0xffffffffu, acc, off);
        if (lane == 0) sh[wi][e] = acc + rb[e];
    }
    __syncwarp();
    float logit = sh[wi][lane];

    float mx = logit;
    #pragma unroll
    for (int off = 16; off; off >>= 1)
        mx = fmaxf(mx, __shfl_xor_sync(0xffffffffu, mx, off));
    float p = expf(logit - mx);
    float sm = p;
    #pragma unroll
    for (int off = 16; off; off >>= 1)
        sm += __shfl_xor_sync(0xffffffffu, sm, off);
    float score = p / sm;

    const int grp = lane >> 2;
    float v0 = __shfl_sync(0xffffffffu, score, grp * 4 + 0);
    float v1 = __shfl_sync(0xffffffffu, score, grp * 4 + 1);
    float v2 = __shfl_sync(0xffffffffu, score, grp * 4 + 2);
    float v3 = __shfl_sync(0xffffffffu, score, grp * 4 + 3);
    float a  = fmaxf(v0, v1), b  = fminf(v0, v1);
    float c  = fmaxf(v2, v3), dd = fminf(v2, v3);
    float top2 = (a >= c) ? (a + fmaxf(b, c)) : (c + fmaxf(a, dd));

    float gsa[8];
    #pragma unroll
    for (int j = 0; j < 8; j++) gsa[j] = __shfl_sync(0xffffffffu, top2, j * 4);
    unsigned keep = 0;
    #pragma unroll
    for (int it = 0; it < 4; it++) {
        float bv = -1e30f; int bj = 0;
        #pragma unroll
        for (int j = 0; j < 8; j++) {
            bool cand = (((keep >> j) & 1u) == 0u) && (gsa[j] > bv);
            if (cand) { bv = gsa[j]; bj = j; }
        }
        keep |= 1u << bj;
    }

    float msc = ((keep >> grp) & 1u) ? score : -1e30f;
    __syncwarp();
    sh[wi][lane] = msc;
    __syncwarp();

    if (lane == 0) {
        #pragma unroll
        for (int kk = 0; kk < K_; kk++) {
            float bv = -1e30f; int be = 0;
            for (int ee = 0; ee < 32; ee++) {
                float s = sh[wi][ee];
                if (s > bv) { bv = s; be = ee; }
            }
            sh[wi][be] = -2e30f;
            g_tidx[t * K_ + kk] = be;
            g_tval[t * K_ + kk] = bv;
            int pos = atomicAdd(&g_cnt[be], 1);
            g_slots[be * T_ + pos] = t * K_ + kk;
        }
    }
}

// ---------------- bias pre-pass: out[t] = sb3 + sum_k gate_k * b3[e_k] ----------------
__global__ __launch_bounds__(256) void moe_bias_kernel(
    const float* __restrict__ b3, const float* __restrict__ sb3,
    float* __restrict__ out)
{
    const int t = blockIdx.x;
    int   ti[K_];
    float tv[K_];
    #pragma unroll
    for (int k = 0; k < K_; k++) { ti[k] = g_tidx[t * K_ + k]; tv[k] = g_tval[t * K_ + k]; }
    for (int n = threadIdx.x * 4; n < D_; n += blockDim.x * 4) {
        float4 v = *(const float4*)(sb3 + n);
        #pragma unroll
        for (int k = 0; k < K_; k++) {
            float4 bb = *(const float4*)(b3 + (size_t)ti[k] * D_ + n);
            v.x = fmaf(tv[k], bb.x, v.x); v.y = fmaf(tv[k], bb.y, v.y);
            v.z = fmaf(tv[k], bb.z, v.z); v.w = fmaf(tv[k], bb.w, v.w);
        }
        *(float4*)(out + (size_t)t * D_ + n) = v;
    }
}

// ======================================================================
// tf32 MMA GEMM kernels. Block tile 64x128x16, 8 warps (2x4), warp 32x32.
// ======================================================================

// ---- shared expert stage 1 (dual B): g_zh = silu((x@sw1+sb1)*(x@sw2+sb2)) ----
__global__ __launch_bounds__(256) void moe_shared_h_kernel(
    const float* __restrict__ x,
    const float* __restrict__ sw1, const float* __restrict__ sb1,
    const float* __restrict__ sw2, const float* __restrict__ sb2)
{
    __shared__ unsigned As[BM * ASTR];
    __shared__ unsigned B1s[BK * BSTR];
    __shared__ unsigned B2s[BK * BSTR];

    const int tid = threadIdx.x;
    const int mb = blockIdx.y * BM, nb = blockIdx.x * BN;
    const int am = tid >> 2, ak = (tid & 3) << 2;
    const int bk = tid >> 4, bn = (tid & 15) << 3;

    const int lane = tid & 31, warp = tid >> 5;
    const int wm = warp >> 2, wn = warp & 3;
    const int grp = lane >> 2, tq = lane & 3;
    const int mbase = wm * 32, nbase = wn * 32;

    const float* Ap  = x   + (size_t)(mb + am) * D_ + ak;
    const float* B1p = sw1 + (size_t)bk * SI_ + nb + bn;
    const float* B2p = sw2 + (size_t)bk * SI_ + nb + bn;

    float c1[2][4][4] = {}, c2[2][4][4] = {};

    float4 av  = *(const float4*)Ap;
    float4 b1a = *(const float4*)B1p,       b1b = *(const float4*)(B1p + 4);
    float4 b2a = *(const float4*)B2p,       b2b = *(const float4*)(B2p + 4);

    for (int k0 = 0; k0 < D_; k0 += BK) {
        As[am * ASTR + ak + 0] = f2tf(av.x); As[am * ASTR + ak + 1] = f2tf(av.y);
        As[am * ASTR + ak + 2] = f2tf(av.z); As[am * ASTR + ak + 3] = f2tf(av.w);
        B1s[bk * BSTR + bn + 0] = f2tf(b1a.x); B1s[bk * BSTR + bn + 1] = f2tf(b1a.y);
        B1s[bk * BSTR + bn + 2] = f2tf(b1a.z); B1s[bk * BSTR + bn + 3] = f2tf(b1a.w);
        B1s[bk * BSTR + bn + 4] = f2tf(b1b.x); B1s[bk * BSTR + bn + 5] = f2tf(b1b.y);
        B1s[bk * BSTR + bn + 6] = f2tf(b1b.z); B1s[bk * BSTR + bn + 7] = f2tf(b1b.w);
        B2s[bk * BSTR + bn + 0] = f2tf(b2a.x); B2s[bk * BSTR + bn + 1] = f2tf(b2a.y);
        B2s[bk * BSTR + bn + 2] = f2tf(b2a.z); B2s[bk * BSTR + bn + 3] = f2tf(b2a.w);
        B2s[bk * BSTR + bn + 4] = f2tf(b2b.x); B2s[bk * BSTR + bn + 5] = f2tf(b2b.y);
        B2s[bk * BSTR + bn + 6] = f2tf(b2b.z); B2s[bk * BSTR + bn + 7] = f2tf(b2b.w);
        __syncthreads();
        if (k0 + BK < D_) {
            av  = *(const float4*)(Ap + k0 + BK);
            b1a = *(const float4*)(B1p + (size_t)(k0 + BK) * SI_);
            b1b = *(const float4*)(B1p + (size_t)(k0 + BK) * SI_ + 4);
            b2a = *(const float4*)(B2p + (size_t)(k0 + BK) * SI_);
            b2b = *(const float4*)(B2p + (size_t)(k0 + BK) * SI_ + 4);
        }
        #pragma unroll
        for (int ks = 0; ks < 2; ks++) {
            unsigned a[2][4];
            #pragma unroll
            for (int im = 0; im < 2; im++) {
                int mr = mbase + im * 16 + grp;
                a[im][0] = As[mr * ASTR + ks * 8 + tq];
                a[im][1] = As[(mr + 8) * ASTR + ks * 8 + tq];
                a[im][2] = As[mr * ASTR + ks * 8 + tq + 4];
                a[im][3] = As[(mr + 8) * ASTR + ks * 8 + tq + 4];
            }
            #pragma unroll
            for (int in = 0; in < 4; in++) {
                int nc = nbase + in * 8 + grp;
                unsigned p0 = B1s[(ks * 8 + tq) * BSTR + nc];
                unsigned p1 = B1s[(ks * 8 + tq + 4) * BSTR + nc];
                unsigned q0 = B2s[(ks * 8 + tq) * BSTR + nc];
                unsigned q1 = B2s[(ks * 8 + tq + 4) * BSTR + nc];
                #pragma unroll
                for (int im = 0; im < 2; im++) {
                    MMA8(c1[im][in], a[im], p0, p1);
                    MMA8(c2[im][in], a[im], q0, q1);
                }
            }
        }
        __syncthreads();
    }

    #pragma unroll
    for (int im = 0; im < 2; im++)
        #pragma unroll
        for (int in = 0; in < 4; in++)
            #pragma unroll
            for (int r = 0; r < 4; r++) {
                int row = mb + mbase + im * 16 + grp + (r >= 2 ? 8 : 0);
                int col = nb + nbase + in * 8 + 2 * tq + (r & 1);
                float h1 = c1[im][in][r] + sb1[col];
                float h2 = c2[im][in][r] + sb2[col];
                float pp = h1 * h2;
                g_zh[(size_t)row * SI_ + col] = pp / (1.f + expf(-pp));
            }
}

// ---- shared expert stage 2: out += g_zh @ sw3 ----
__global__ __launch_bounds__(256) void moe_out_init_kernel(
    const float* __restrict__ sw3, float* __restrict__ out)
{
    __shared__ unsigned As[BM * ASTR];
    __shared__ unsigned Bs[BK * BSTR];

    const int tid = threadIdx.x;
    const int mb = blockIdx.y * BM, nb = blockIdx.x * BN;
    const int am = tid >> 2, ak = (tid & 3) << 2;
    const int bk = tid >> 4, bn = (tid & 15) << 3;

    const int lane = tid & 31, warp = tid >> 5;
    const int wm = warp >> 2, wn = warp & 3;
    const int grp = lane >> 2, tq = lane & 3;
    const int mbase = wm * 32, nbase = wn * 32;

    const float* Ap = g_zh + (size_t)(mb + am) * SI_ + ak;
    const float* Bp = sw3  + (size_t)bk * D_ + nb + bn;

    float c[2][4][4] = {};
    float4 av = *(const float4*)Ap;
    float4 ba = *(const float4*)Bp, bb = *(const float4*)(Bp + 4);

    for (int k0 = 0; k0 < SI_; k0 += BK) {
        As[am * ASTR + ak + 0] = f2tf(av.x); As[am * ASTR + ak + 1] = f2tf(av.y);
        As[am * ASTR + ak + 2] = f2tf(av.z); As[am * ASTR + ak + 3] = f2tf(av.w);
        Bs[bk * BSTR + bn + 0] = f2tf(ba.x); Bs[bk * BSTR + bn + 1] = f2tf(ba.y);
        Bs[bk * BSTR + bn + 2] = f2tf(ba.z); Bs[bk * BSTR + bn + 3] = f2tf(ba.w);
        Bs[bk * BSTR + bn + 4] = f2tf(bb.x); Bs[bk * BSTR + bn + 5] = f2tf(bb.y);
        Bs[bk * BSTR + bn + 6] = f2tf(bb.z); Bs[bk * BSTR + bn + 7] = f2tf(bb.w);
        __syncthreads();
        if (k0 + BK < SI_) {
            av = *(const float4*)(Ap + k0 + BK);
            ba = *(const float4*)(Bp + (size_t)(k0 + BK) * D_);
            bb = *(const float4*)(Bp + (size_t)(k0 + BK) * D_ + 4);
        }
        #pragma unroll
        for (int ks = 0; ks < 2; ks++) {
            unsigned a[2][4];
            #pragma unroll
            for (int im = 0; im < 2; im++) {
                int mr = mbase + im * 16 + grp;
                a[im][0] = As[mr * ASTR + ks * 8 + tq];
                a[im][1] = As[(mr + 8) * ASTR + ks * 8 + tq];
                a[im][2] = As[mr * ASTR + ks * 8 + tq + 4];
                a[im][3] = As[(mr + 8) * ASTR + ks * 8 + tq + 4];
            }
            #pragma unroll
            for (int in = 0; in < 4; in++) {
                int nc = nbase + in * 8 + grp;
                unsigned p0 = Bs[(ks * 8 + tq) * BSTR + nc];
                unsigned p1 = Bs[(ks * 8 + tq + 4) * BSTR + nc];
                #pragma unroll
                for (int im = 0; im < 2; im++)
                    MMA8(c[im][in], a[im], p0, p1);
            }
        }
        __syncthreads();
    }

    #pragma unroll
    for (int im = 0; im < 2; im++)
        #pragma unroll
        for (int in = 0; in < 4; in++)
            #pragma unroll
            for (int r = 0; r < 4; r++) {
                int row = mb + mbase + im * 16 + grp + (r >= 2 ? 8 : 0);
                int col = nb + nbase + in * 8 + 2 * tq + (r & 1);
                out[(size_t)row * D_ + col] += c[im][in][r];
            }
}

// ---- routed stage 1 (dual B, gathered rows): g_hs = gate*silu((xW1+b1)*(xW2+b2)) ----
__global__ __launch_bounds__(256) void moe_routed_h_kernel(
    const float* __restrict__ x,
    const float* __restrict__ W1, const float* __restrict__ b1,
    const float* __restrict__ W2, const float* __restrict__ b2)
{
    const int e   = blockIdx.z;
    const int cnt = g_cnt[e];
    const int mb  = blockIdx.y * BM;
    if (mb >= cnt) return;
    const int nb  = blockIdx.x * BN;

    __shared__ unsigned As[BM * ASTR];
    __shared__ unsigned B1s[BK * BSTR];
    __shared__ unsigned B2s[BK * BSTR];
    __shared__ int slotS[BM];

    const int tid = threadIdx.x;
    if (tid < BM) {
        int m = mb + tid;
        slotS[tid] = (m < cnt) ? g_slots[e * T_ + m] : g_slots[e * T_];
    }
    __syncthreads();

    const int am = tid >> 2, ak = (tid & 3) << 2;
    const int bk = tid >> 4, bn = (tid & 15) << 3;
    const int lane = tid & 31, warp = tid >> 5;
    const int wm = warp >> 2, wn = warp & 3;
    const int grp = lane >> 2, tq = lane & 3;
    const int mbase = wm * 32, nbase = wn * 32;

    const float* Ap  = x  + (size_t)(slotS[am] / K_) * D_ + ak;
    const float* B1p = W1 + (size_t)e * D_ * I_ + (size_t)bk * I_ + nb + bn;
    const float* B2p = W2 + (size_t)e * D_ * I_ + (size_t)bk * I_ + nb + bn;

    float c1[2][4][4] = {}, c2[2][4][4] = {};
    float4 av  = *(const float4*)Ap;
    float4 b1a = *(const float4*)B1p, b1b = *(const float4*)(B1p + 4);
    float4 b2a = *(const float4*)B2p, b2b = *(const float4*)(B2p + 4);

    for (int k0 = 0; k0 < D_; k0 += BK) {
        As[am * ASTR + ak + 0] = f2tf(av.x); As[am * ASTR + ak + 1] = f2tf(av.y);
        As[am * ASTR + ak + 2] = f2tf(av.z); As[am * ASTR + ak + 3] = f2tf(av.w);
        B1s[bk * BSTR + bn + 0] = f2tf(b1a.x); B1s[bk * BSTR + bn + 1] = f2tf(b1a.y);
        B1s[bk * BSTR + bn + 2] = f2tf(b1a.z); B1s[bk * BSTR + bn + 3] = f2tf(b1a.w);
        B1s[bk * BSTR + bn + 4] = f2tf(b1b.x); B1s[bk * BSTR + bn + 5] = f2tf(b1b.y);
        B1s[bk * BSTR + bn + 6] = f2tf(b1b.z); B1s[bk * BSTR + bn + 7] = f2tf(b1b.w);
        B2s[bk * BSTR + bn + 0] = f2tf(b2a.x); B2s[bk * BSTR + bn + 1] = f2tf(b2a.y);
        B2s[bk * BSTR + bn + 2] = f2tf(b2a.z); B2s[bk * BSTR + bn + 3] = f2tf(b2a.w);
        B2s[bk * BSTR + bn + 4] = f2tf(b2b.x); B2s[bk * BSTR + bn + 5] = f2tf(b2b.y);
        B2s[bk * BSTR + bn + 6] = f2tf(b2b.z); B2s[bk * BSTR + bn + 7] = f2tf(b2b.w);
        __syncthreads();
        if (k0 + BK < D_) {
            av  = *(const float4*)(Ap + k0 + BK);
            b1a = *(const float4*)(B1p + (size_t)(k0 + BK) * I_);
            b1b = *(const float4*)(B1p + (size_t)(k0 + BK) * I_ + 4);
            b2a = *(const float4*)(B2p + (size_t)(k0 + BK) * I_);
            b2b = *(const float4*)(B2p + (size_t)(k0 + BK) * I_ + 4);
        }
        #pragma unroll
        for (int ks = 0; ks < 2; ks++) {
            unsigned a[2][4];
            #pragma unroll
            for (int im = 0; im < 2; im++) {
                int mr = mbase + im * 16 + grp;
                a[im][0] = As[mr * ASTR + ks * 8 + tq];
                a[im][1] = As[(mr + 8) * ASTR + ks * 8 + tq];
                a[im][2] = As[mr * ASTR + ks * 8 + tq + 4];
                a[im][3] = As[(mr + 8) * ASTR + ks * 8 + tq + 4];
            }
            #pragma unroll
            for (int in = 0; in < 4; in++) {
                int nc = nbase + in * 8 + grp;
                unsigned p0 = B1s[(ks * 8 + tq) * BSTR + nc];
                unsigned p1 = B1s[(ks * 8 + tq + 4) * BSTR + nc];
                unsigned q0 = B2s[(ks * 8 + tq) * BSTR + nc];
                unsigned q1 = B2s[(ks * 8 + tq + 4) * BSTR + nc];
                #pragma unroll
                for (int im = 0; im < 2; im++) {
                    MMA8(c1[im][in], a[im], p0, p1);
                    MMA8(c2[im][in], a[im], q0, q1);
                }
            }
        }
        __syncthreads();
    }

    #pragma unroll
    for (int im = 0; im < 2; im++)
        #pragma unroll
        for (int h = 0; h < 2; h++) {
            int lr = mbase + im * 16 + grp + h * 8;
            bool valid = (mb + lr) < cnt;
            int s = slotS[lr];
            float gv = g_tval[s];
            #pragma unroll
            for (int in = 0; in < 4; in++)
                #pragma unroll
                for (int q = 0; q < 2; q++) {
                    int r = h * 2 + q;
                    int col = nb + nbase + in * 8 + 2 * tq + q;
                    float h1 = c1[im][in][r] + b1[(size_t)e * I_ + col];
                    float h2 = c2[im][in][r] + b2[(size_t)e * I_ + col];
                    float pp = h1 * h2;
                    float hv = gv * pp / (1.f + expf(-pp));
                    if (valid) g_hs[(size_t)s * I_ + col] = hv;
                }
        }
}

// ---- routed stage 2: out += g_hs @ W3[e] (scatter atomicAdd) ----
__global__ __launch_bounds__(256) void moe_routed_out_kernel(
    const float* __restrict__ W3, float* __restrict__ out)
{
    const int e   = blockIdx.z;
    const int cnt = g_cnt[e];
    const int mb  = blockIdx.y * BM;
    if (mb >= cnt) return;
    const int nb  = blockIdx.x * BN;

    __shared__ unsigned As[BM * ASTR];
    __shared__ unsigned Bs[BK * BSTR];
    __shared__ int slotS[BM];

    const int tid = threadIdx.x;
    if (tid < BM) {
        int m = mb + tid;
        slotS[tid] = (m < cnt) ? g_slots[e * T_ + m] : g_slots[e * T_];
    }
    __syncthreads();

    const int am = tid >> 2, ak = (tid & 3) << 2;
    const int bk = tid >> 4, bn = (tid & 15) << 3;
    const int lane = tid & 31, warp = tid >> 5;
    const int wm = warp >> 2, wn = warp & 3;
    const int grp = lane >> 2, tq = lane & 3;
    const int mbase = wm * 32, nbase = wn * 32;

    const float* Ap = g_hs + (size_t)slotS[am] * I_ + ak;
    const float* Bp = W3 + (size_t)e * I_ * D_ + (size_t)bk * D_ + nb + bn;

    float c[2][4][4] = {};
    float4 av = *(const float4*)Ap;
    float4 ba = *(const float4*)Bp, bb = *(const float4*)(Bp + 4);

    for (int k0 = 0; k0 < I_; k0 += BK) {
        As[am * ASTR + ak + 0] = f2tf(av.x); As[am * ASTR + ak + 1] = f2tf(av.y);
        As[am * ASTR + ak + 2] = f2tf(av.z); As[am * ASTR + ak + 3] = f2tf(av.w);
        Bs[bk * BSTR + bn + 0] = f2tf(ba.x); Bs[bk * BSTR + bn + 1] = f2tf(ba.y);
        Bs[bk * BSTR + bn + 2] = f2tf(ba.z); Bs[bk * BSTR + bn + 3] = f2tf(ba.w);
        Bs[bk * BSTR + bn + 4] = f2tf(bb.x); Bs[bk * BSTR + bn + 5] = f2tf(bb.y);
        Bs[bk * BSTR + bn + 6] = f2tf(bb.z); Bs[bk * BSTR + bn + 7] = f2tf(bb.w);
        __syncthreads();
        if (k0 + BK < I_) {
            av = *(const float4*)(Ap + k0 + BK);
            ba = *(const float4*)(Bp + (size_t)(k0 + BK) * D_);
            bb = *(const float4*)(Bp + (size_t)(k0 + BK) * D_ + 4);
        }
        #pragma unroll
        for (int ks = 0; ks < 2; ks++) {
            unsigned a[2][4];
            #pragma unroll
            for (int im = 0; im < 2; im++) {
                int mr = mbase + im * 16 + grp;
                a[im][0] = As[mr * ASTR + ks * 8 + tq];
                a[im][1] = As[(mr + 8) * ASTR + ks * 8 + tq];
                a[im][2] = As[mr * ASTR + ks * 8 + tq + 4];
                a[im][3] = As[(mr + 8) * ASTR + ks * 8 + tq + 4];
            }
            #pragma unroll
            for (int in = 0; in < 4; in++) {
                int nc = nbase + in * 8 + grp;
                unsigned p0 = Bs[(ks * 8 + tq) * BSTR + nc];
                unsigned p1 = Bs[(ks * 8 + tq + 4) * BSTR + nc];
                #pragma unroll
                for (int im = 0; im < 2; im++)
                    MMA8(c[im][in], a[im], p0, p1);
            }
        }
        __syncthreads();
    }

    #pragma unroll
    for (int im = 0; im < 2; im++)
        #pragma unroll
        for (int h = 0; h < 2; h++) {
            int lr = mbase + im * 16 + grp + h * 8;
            if ((mb + lr) < cnt) {
                int t = slotS[lr] / K_;
                #pragma unroll
                for (int in = 0; in < 4; in++)
                    #pragma unroll
                    for (int q = 0; q < 2; q++) {
                        int col = nb + nbase + in * 8 + 2 * tq + q;
                        atomicAdd(&out[(size_t)t * D_ + col], c[im][in][h * 2 + q]);
                    }
            }
        }
}

// ---------------- launch ----------------
extern "C" void kernel_launch(void* const* d_in, const int* in_sizes, int n_in,
                              void* d_out, int out_size)
{
    (void)in_sizes; (void)n_in; (void)out_size;
    const float* x   = (const float*)d_in[0];
    const float* rw  = (const float*)d_in[1];
    const float* rb  = (const float*)d_in[2];
    const float* W1  = (const float*)d_in[3];
    const float* b1  = (const float*)d_in[4];
    const float* W2  = (const float*)d_in[5];
    const float* b2  = (const float*)d_in[6];
    const float* W3  = (const float*)d_in[7];
    const float* b3  = (const float*)d_in[8];
    const float* sw1 = (const float*)d_in[9];
    const float* sb1 = (const float*)d_in[10];
    const float* sw2 = (const float*)d_in[11];
    const float* sb2 = (const float*)d_in[12];
    const float* sw3 = (const float*)d_in[13];
    const float* sb3 = (const float*)d_in[14];
    float* out = (float*)d_out;

    moe_init_kernel<<<1, 32>>>();
    moe_router_kernel<<<T_ / 8, 256>>>(x, rw, rb);
    moe_bias_kernel<<<T_, 256>>>(b3, sb3, out);
    moe_shared_h_kernel<<<dim3(SI_ / BN, T_ / BM), 256>>>(x, sw1, sb1, sw2, sb2);
    moe_out_init_kernel<<<dim3(D_ / BN, T_ / BM), 256>>>(sw3, out);
    moe_routed_h_kernel<<<dim3(I_ / BN, T_ / BM, E_), 256>>>(x, W1, b1, W2, b2);
    moe_routed_out_kernel<<<dim3(D_ / BN, T_ / BM, E_), 256>>>(W3, out);
}